// round 1
// baseline (speedup 1.0000x reference)
#include <cuda_runtime.h>
#include <cuda_bf16.h>
#include <cstdint>

// Shapes (fixed for this problem)
#define N_TOTAL (64 * 4096)      // 262144 nodes
#define NHID    128
#define NN      4096             // nodes per graph == w3 dim
#define MB      64               // batch (graphs)

// ---------------- scratch (device globals; no allocation allowed) ----------
__device__ float g_agg1[N_TOTAL];
__device__ float g_deg [N_TOTAL];
__device__ float g_s   [N_TOTAL];
__device__ float g_t   [N_TOTAL];
__device__ float g_agg2[N_TOTAL];
__device__ float g_h2  [N_TOTAL];   // tanh(output1), A matrix of final GEMM

// ---------------- accurate rational tanh (1 MUFU + ~13 FMA) ----------------
// Eigen/XLA minimax rational, fp32-accurate on the clamp range.
__device__ __forceinline__ float tanh_fast(float x) {
    float xc = fminf(fmaxf(x, -7.99881172f), 7.99881172f);
    float x2 = xc * xc;
    float p = fmaf(x2, -2.76076847742355e-16f, 2.00018790482477e-13f);
    p = fmaf(p, x2, -8.60467152213735e-11f);
    p = fmaf(p, x2,  5.12229709037114e-08f);
    p = fmaf(p, x2,  1.48572235717979e-05f);
    p = fmaf(p, x2,  6.37261928875436e-04f);
    p = fmaf(p, x2,  4.89352455891786e-03f);
    p = p * xc;
    float q = fmaf(x2, 1.19825839466702e-06f, 1.18534705686654e-04f);
    q = fmaf(q, x2, 2.26843463243900e-03f);
    q = fmaf(q, x2, 4.89352518554385e-03f);
    return __fdividef(p, q);
}

// ---------------- kernel 0: zero scratch ------------------------------------
__global__ void k_zero(int n) {
    int i = blockIdx.x * blockDim.x + threadIdx.x;
    if (i < n) {
        g_agg1[i] = 0.0f;
        g_deg[i]  = 0.0f;
        g_agg2[i] = 0.0f;
    }
}

// ---------------- kernel 1: edge scatter pass 1 (agg1, deg) -----------------
__global__ void k_edge1(const float* __restrict__ feat,
                        const int* __restrict__ src,
                        const int* __restrict__ dst, int E) {
    int e = blockIdx.x * blockDim.x + threadIdx.x;
    if (e < E) {
        int s = src[e];
        int d = dst[e];
        atomicAdd(&g_agg1[d], __ldg(&feat[s]));
        atomicAdd(&g_deg[d], 1.0f);
    }
}

// ---------------- kernel 2: per-node 128-wide tanh layer --------------------
// s[n] = sum_j tanh(f*ws1[j]+g*wn1[j]+b1[j]) * ws2[j]
// t[n] = sum_j tanh(...) * wn2[j]
__global__ __launch_bounds__(256) void k_node1(
        const float* __restrict__ feat,
        const float* __restrict__ ws1, const float* __restrict__ wn1,
        const float* __restrict__ b1,
        const float* __restrict__ ws2, const float* __restrict__ wn2,
        int n_total) {
    __shared__ float4 wA[NHID];   // {ws1, wn1, b1, ws2}
    __shared__ float  wB[NHID];   // wn2
    int t = threadIdx.x;
    if (t < NHID) {
        wA[t] = make_float4(ws1[t], wn1[t], b1[t], ws2[t]);
        wB[t] = wn2[t];
    }
    __syncthreads();

    int n = blockIdx.x * blockDim.x + t;
    if (n >= n_total) return;

    float f  = feat[n];
    float dg = g_deg[n];
    float g  = __fdividef(g_agg1[n], fmaxf(dg, 1.0f));

    float sacc = 0.0f, tacc = 0.0f;
#pragma unroll 8
    for (int j = 0; j < NHID; j++) {
        float4 w = wA[j];
        float x = fmaf(f, w.x, fmaf(g, w.y, w.z));
        float r = tanh_fast(x);
        sacc = fmaf(r, w.w, sacc);
        tacc = fmaf(r, wB[j], tacc);
    }
    g_s[n] = sacc;
    g_t[n] = tacc;
}

// ---------------- kernel 3: edge scatter pass 2 (agg2 of t) -----------------
__global__ void k_edge2(const int* __restrict__ src,
                        const int* __restrict__ dst, int E) {
    int e = blockIdx.x * blockDim.x + threadIdx.x;
    if (e < E) {
        atomicAdd(&g_agg2[dst[e]], __ldg(&g_t[src[e]]));
    }
}

// ---------------- kernel 4: out1, h2 = tanh(out1), init out2 with b3 --------
__global__ void k_node2(const float* __restrict__ b2,
                        const float* __restrict__ b3,
                        float* __restrict__ out, int n_total) {
    int n = blockIdx.x * blockDim.x + threadIdx.x;
    if (n < n_total) {
        float o = g_s[n] + __fdividef(g_agg2[n], fmaxf(g_deg[n], 1.0f)) + b2[0];
        out[n] = o;                          // output1
        g_h2[n] = tanh_fast(o);
        out[n_total + n] = b3[n & (NN - 1)]; // init output2 = b3 broadcast
    }
}

// ---------------- kernel 5: GEMM output2 += h2 @ w3 (bf16 hi/lo split) ------
// C[64,4096] += A[64,4096] * B[4096,4096], fp32 in/out.
// Split each fp32 into bf16 hi+lo; C += Ah*Bh + Ah*Bl + Al*Bh via
// mma.sync.m16n8k16.bf16. Split-K=4 with fp32 atomics into out2.
#define GEMM_BN 64
#define GEMM_KSPLIT 4

__device__ __forceinline__ void mma_bf16(float c[4], uint32_t a0, uint32_t a1,
                                         uint32_t a2, uint32_t a3,
                                         uint32_t b0, uint32_t b1) {
    asm volatile(
        "mma.sync.aligned.m16n8k16.row.col.f32.bf16.bf16.f32 "
        "{%0,%1,%2,%3}, {%4,%5,%6,%7}, {%8,%9}, {%0,%1,%2,%3};\n"
        : "+f"(c[0]), "+f"(c[1]), "+f"(c[2]), "+f"(c[3])
        : "r"(a0), "r"(a1), "r"(a2), "r"(a3), "r"(b0), "r"(b1));
}

__device__ __forceinline__ unsigned short f2bf_hi(float v) {
    __nv_bfloat16 h = __float2bfloat16(v);
    return *reinterpret_cast<unsigned short*>(&h);
}

__global__ __launch_bounds__(128) void k_gemm(const float* __restrict__ w3,
                                              float* __restrict__ out2) {
    __shared__ __align__(16) unsigned short sAh[MB][16], sAl[MB][16];  // [m][k]
    __shared__ __align__(16) unsigned short sBh[16][GEMM_BN], sBl[16][GEMM_BN]; // [k][n]

    int tid  = threadIdx.x;
    int warp = tid >> 5;
    int lane = tid & 31;
    int g    = lane >> 2;      // group id
    int tg   = lane & 3;       // thread-in-group
    int n0   = blockIdx.x * GEMM_BN;
    int kb   = blockIdx.y * (NN / GEMM_KSPLIT);

    float acc[4][2][4];
#pragma unroll
    for (int mi = 0; mi < 4; mi++)
#pragma unroll
        for (int ni = 0; ni < 2; ni++)
#pragma unroll
            for (int r = 0; r < 4; r++) acc[mi][ni][r] = 0.0f;

    for (int kk = 0; kk < NN / GEMM_KSPLIT; kk += 16) {
        int k0 = kb + kk;
        __syncthreads();
        // stage A tile 64x16 (h2), split to bf16 hi/lo
#pragma unroll
        for (int i = tid; i < MB * 16; i += 128) {
            int r = i >> 4, c = i & 15;
            float v = g_h2[r * NN + k0 + c];
            __nv_bfloat16 h = __float2bfloat16(v);
            float lo = v - __bfloat162float(h);
            sAh[r][c] = *reinterpret_cast<unsigned short*>(&h);
            sAl[r][c] = f2bf_hi(lo);
        }
        // stage B tile 16x64 (w3), split
#pragma unroll
        for (int i = tid; i < 16 * GEMM_BN; i += 128) {
            int r = i >> 6, c = i & 63;
            float v = w3[(size_t)(k0 + r) * NN + n0 + c];
            __nv_bfloat16 h = __float2bfloat16(v);
            float lo = v - __bfloat162float(h);
            sBh[r][c] = *reinterpret_cast<unsigned short*>(&h);
            sBl[r][c] = f2bf_hi(lo);
        }
        __syncthreads();

        const uint32_t* pAh = reinterpret_cast<const uint32_t*>(&sAh[0][0]);
        const uint32_t* pAl = reinterpret_cast<const uint32_t*>(&sAl[0][0]);

        uint32_t aH[4][4], aL[4][4];
#pragma unroll
        for (int mi = 0; mi < 4; mi++) {
            int r0 = mi * 16 + g;
            aH[mi][0] = pAh[(r0 * 16 + 2 * tg) >> 1];
            aH[mi][1] = pAh[((r0 + 8) * 16 + 2 * tg) >> 1];
            aH[mi][2] = pAh[(r0 * 16 + 2 * tg + 8) >> 1];
            aH[mi][3] = pAh[((r0 + 8) * 16 + 2 * tg + 8) >> 1];
            aL[mi][0] = pAl[(r0 * 16 + 2 * tg) >> 1];
            aL[mi][1] = pAl[((r0 + 8) * 16 + 2 * tg) >> 1];
            aL[mi][2] = pAl[(r0 * 16 + 2 * tg + 8) >> 1];
            aL[mi][3] = pAl[((r0 + 8) * 16 + 2 * tg + 8) >> 1];
        }
        uint32_t bH[2][2], bL[2][2];
#pragma unroll
        for (int ni = 0; ni < 2; ni++) {
            int col = warp * 16 + ni * 8 + g;
            bH[ni][0] = (uint32_t)sBh[2 * tg][col]     | ((uint32_t)sBh[2 * tg + 1][col] << 16);
            bH[ni][1] = (uint32_t)sBh[2 * tg + 8][col] | ((uint32_t)sBh[2 * tg + 9][col] << 16);
            bL[ni][0] = (uint32_t)sBl[2 * tg][col]     | ((uint32_t)sBl[2 * tg + 1][col] << 16);
            bL[ni][1] = (uint32_t)sBl[2 * tg + 8][col] | ((uint32_t)sBl[2 * tg + 9][col] << 16);
        }
#pragma unroll
        for (int mi = 0; mi < 4; mi++)
#pragma unroll
            for (int ni = 0; ni < 2; ni++) {
                mma_bf16(acc[mi][ni], aH[mi][0], aH[mi][1], aH[mi][2], aH[mi][3],
                         bH[ni][0], bH[ni][1]);
                mma_bf16(acc[mi][ni], aH[mi][0], aH[mi][1], aH[mi][2], aH[mi][3],
                         bL[ni][0], bL[ni][1]);
                mma_bf16(acc[mi][ni], aL[mi][0], aL[mi][1], aL[mi][2], aL[mi][3],
                         bH[ni][0], bH[ni][1]);
            }
    }

    // epilogue: atomic accumulate (split-K)
#pragma unroll
    for (int mi = 0; mi < 4; mi++) {
        int row = mi * 16 + g;
#pragma unroll
        for (int ni = 0; ni < 2; ni++) {
            int col = n0 + warp * 16 + ni * 8 + 2 * tg;
            atomicAdd(&out2[(size_t)row * NN + col],       acc[mi][ni][0]);
            atomicAdd(&out2[(size_t)row * NN + col + 1],   acc[mi][ni][1]);
            atomicAdd(&out2[(size_t)(row + 8) * NN + col],     acc[mi][ni][2]);
            atomicAdd(&out2[(size_t)(row + 8) * NN + col + 1], acc[mi][ni][3]);
        }
    }
}

// ---------------- launch ----------------------------------------------------
extern "C" void kernel_launch(void* const* d_in, const int* in_sizes, int n_in,
                              void* d_out, int out_size) {
    const float* feat = (const float*)d_in[0];
    const int*   src  = (const int*)d_in[1];
    const int*   dst  = (const int*)d_in[2];
    const float* ws1  = (const float*)d_in[3];
    const float* wn1  = (const float*)d_in[4];
    const float* b1   = (const float*)d_in[5];
    const float* ws2  = (const float*)d_in[6];
    const float* wn2  = (const float*)d_in[7];
    const float* b2   = (const float*)d_in[8];
    const float* w3   = (const float*)d_in[9];
    const float* b3   = (const float*)d_in[10];
    float* out = (float*)d_out;

    int N = in_sizes[0];   // 262144
    int E = in_sizes[1];   // 2097152

    k_zero<<<(N + 255) / 256, 256>>>(N);
    k_edge1<<<(E + 255) / 256, 256>>>(feat, src, dst, E);
    k_node1<<<(N + 255) / 256, 256>>>(feat, ws1, wn1, b1, ws2, wn2, N);
    k_edge2<<<(E + 255) / 256, 256>>>(src, dst, E);
    k_node2<<<(N + 255) / 256, 256>>>(b2, b3, out, N);

    dim3 grid(NN / GEMM_BN, GEMM_KSPLIT);
    k_gemm<<<grid, 128>>>(w3, out + N);
}

// round 2
// speedup vs baseline: 1.2635x; 1.2635x over previous
#include <cuda_runtime.h>
#include <cuda_bf16.h>
#include <cstdint>

// Shapes (fixed for this problem)
#define N_TOTAL (64 * 4096)      // 262144 nodes
#define NHID    128
#define NN      4096             // nodes per graph == w3 dim
#define MB      64               // batch (graphs)

// ---------------- scratch (device globals; no allocation allowed) ----------
__device__ float g_agg1[N_TOTAL];
__device__ float g_deg [N_TOTAL];
__device__ float g_s   [N_TOTAL];
__device__ float g_t   [N_TOTAL];
__device__ float g_agg2[N_TOTAL];
__device__ float g_h2  [N_TOTAL];   // tanh(output1), A matrix of final GEMM

#define C_2LOG2E 2.88539008177792681f   // 2*log2(e)

// tanh via MUFU: input is PRESCALED xp = 2*log2e*x.
// tanh(x) = 1 - 2/(exp(2x)+1);  exp(2x) = exp2(xp).
// inf/0 corner cases saturate correctly to +/-1 through rcp.approx.
__device__ __forceinline__ float tanh_exp2(float xp) {
    float e;
    asm("ex2.approx.f32 %0, %1;" : "=f"(e) : "f"(xp));
    float r;
    asm("rcp.approx.f32 %0, %1;" : "=f"(r) : "f"(e + 1.0f));
    return fmaf(-2.0f, r, 1.0f);
}

// ---------------- kernel 0: zero scratch (vectorized) -----------------------
__global__ void k_zero(int n4) {
    int i = blockIdx.x * blockDim.x + threadIdx.x;
    if (i < n4) {
        float4 z = make_float4(0.f, 0.f, 0.f, 0.f);
        reinterpret_cast<float4*>(g_agg1)[i] = z;
        reinterpret_cast<float4*>(g_deg )[i] = z;
        reinterpret_cast<float4*>(g_agg2)[i] = z;
    }
}

// ---------------- kernel 1: edge scatter pass 1 (agg1, deg) -----------------
__global__ void k_edge1(const float* __restrict__ feat,
                        const int* __restrict__ src,
                        const int* __restrict__ dst, int E) {
    int e = blockIdx.x * blockDim.x + threadIdx.x;
    if (e < E) {
        int s = src[e];
        int d = dst[e];
        atomicAdd(&g_agg1[d], __ldg(&feat[s]));
        atomicAdd(&g_deg[d], 1.0f);
    }
}

// ---------------- kernel 2: per-node 128-wide tanh layer --------------------
__global__ __launch_bounds__(256) void k_node1(
        const float* __restrict__ feat,
        const float* __restrict__ ws1, const float* __restrict__ wn1,
        const float* __restrict__ b1,
        const float* __restrict__ ws2, const float* __restrict__ wn2,
        int n_total) {
    __shared__ float4 wA[NHID];   // {C*ws1, C*wn1, C*b1, ws2}  (prescaled)
    __shared__ float  wB[NHID];   // wn2
    int t = threadIdx.x;
    if (t < NHID) {
        wA[t] = make_float4(C_2LOG2E * ws1[t], C_2LOG2E * wn1[t],
                            C_2LOG2E * b1[t], ws2[t]);
        wB[t] = wn2[t];
    }
    __syncthreads();

    int n = blockIdx.x * blockDim.x + t;
    if (n >= n_total) return;

    float f  = feat[n];
    float dg = g_deg[n];
    float g  = __fdividef(g_agg1[n], fmaxf(dg, 1.0f));

    float sacc = 0.0f, tacc = 0.0f;
#pragma unroll 8
    for (int j = 0; j < NHID; j++) {
        float4 w = wA[j];
        float xp = fmaf(f, w.x, fmaf(g, w.y, w.z));
        float r = tanh_exp2(xp);
        sacc = fmaf(r, w.w, sacc);
        tacc = fmaf(r, wB[j], tacc);
    }
    g_s[n] = sacc;
    g_t[n] = tacc;
}

// ---------------- kernel 3: edge scatter pass 2 (agg2 of t) -----------------
__global__ void k_edge2(const int* __restrict__ src,
                        const int* __restrict__ dst, int E) {
    int e = blockIdx.x * blockDim.x + threadIdx.x;
    if (e < E) {
        atomicAdd(&g_agg2[dst[e]], __ldg(&g_t[src[e]]));
    }
}

// ---------------- kernel 4: out1, h2 = tanh(out1), init out2 with b3 --------
__global__ void k_node2(const float* __restrict__ b2,
                        const float* __restrict__ b3,
                        float* __restrict__ out, int n_total) {
    int n = blockIdx.x * blockDim.x + threadIdx.x;
    if (n < n_total) {
        float o = g_s[n] + __fdividef(g_agg2[n], fmaxf(g_deg[n], 1.0f)) + b2[0];
        out[n] = o;                          // output1
        g_h2[n] = tanh_exp2(C_2LOG2E * o);
        out[n_total + n] = b3[n & (NN - 1)]; // init output2 = b3 broadcast
    }
}

// ---------------- kernel 5: GEMM output2 += h2 @ w3 (bf16 hi/lo split) ------
// C[64,4096] += A[64,4096] * B[4096,4096], fp32 in/out, rel err ~2^-17.
// 3 passes: Ah*Bh + Ah*Bl + Al*Bh via mma.m16n8k16.bf16.
// Grid: 32 n-tiles (BN=128) x KSPLIT=16 (K range 256 per block, 16 chunks of 16).
// float4 register prefetch + double-buffered smem, ldmatrix fragment loads,
// fp32 atomic split-K epilogue.
#define GEMM_BN 128
#define GEMM_KSPLIT 16
#define GEMM_KRANGE (NN / GEMM_KSPLIT)   // 256
#define GEMM_NCHUNK (GEMM_KRANGE / 16)   // 16

__device__ __forceinline__ void mma_bf16(float c[4], const uint32_t a[4],
                                         const uint32_t b[2]) {
    asm volatile(
        "mma.sync.aligned.m16n8k16.row.col.f32.bf16.bf16.f32 "
        "{%0,%1,%2,%3}, {%4,%5,%6,%7}, {%8,%9}, {%0,%1,%2,%3};\n"
        : "+f"(c[0]), "+f"(c[1]), "+f"(c[2]), "+f"(c[3])
        : "r"(a[0]), "r"(a[1]), "r"(a[2]), "r"(a[3]), "r"(b[0]), "r"(b[1]));
}

__device__ __forceinline__ void ldsm_x4(uint32_t r[4], uint32_t addr) {
    asm volatile("ldmatrix.sync.aligned.m8n8.x4.shared.b16 {%0,%1,%2,%3}, [%4];"
                 : "=r"(r[0]), "=r"(r[1]), "=r"(r[2]), "=r"(r[3]) : "r"(addr));
}
__device__ __forceinline__ void ldsm_x2t(uint32_t r[2], uint32_t addr) {
    asm volatile("ldmatrix.sync.aligned.m8n8.x2.trans.shared.b16 {%0,%1}, [%2];"
                 : "=r"(r[0]), "=r"(r[1]) : "r"(addr));
}

// split two floats into packed bf16 hi pair + bf16 lo pair
__device__ __forceinline__ void split2(float a, float b,
                                       uint32_t& hi, uint32_t& lo) {
    __nv_bfloat16 ha = __float2bfloat16_rn(a);
    __nv_bfloat16 hb = __float2bfloat16_rn(b);
    float la = a - __bfloat162float(ha);
    float lb = b - __bfloat162float(hb);
    __nv_bfloat16 hla = __float2bfloat16_rn(la);
    __nv_bfloat16 hlb = __float2bfloat16_rn(lb);
    hi = (uint32_t)*reinterpret_cast<unsigned short*>(&ha) |
         ((uint32_t)*reinterpret_cast<unsigned short*>(&hb) << 16);
    lo = (uint32_t)*reinterpret_cast<unsigned short*>(&hla) |
         ((uint32_t)*reinterpret_cast<unsigned short*>(&hlb) << 16);
}

__global__ __launch_bounds__(256) void k_gemm(const float* __restrict__ w3,
                                              float* __restrict__ out2) {
    __shared__ __align__(16) unsigned short sAh[2][MB][16], sAl[2][MB][16];
    __shared__ __align__(16) unsigned short sBh[2][16][GEMM_BN], sBl[2][16][GEMM_BN];

    int tid  = threadIdx.x;
    int warp = tid >> 5;          // 0..7
    int lane = tid & 31;
    int g    = lane >> 2;
    int tg   = lane & 3;
    int n0   = blockIdx.x * GEMM_BN;
    int kb   = blockIdx.y * GEMM_KRANGE;

    // staging coordinates
    int rA  = tid >> 2;            // 0..63
    int cA  = (tid & 3) * 4;       // 0,4,8,12
    int rB  = tid >> 5;            // 0..7  (and +8 for second float4)
    int cB  = (tid & 31) * 4;      // 0..124

    float acc[4][2][4];
#pragma unroll
    for (int mi = 0; mi < 4; mi++)
#pragma unroll
        for (int ni = 0; ni < 2; ni++)
#pragma unroll
            for (int r = 0; r < 4; r++) acc[mi][ni][r] = 0.0f;

    // prefetch chunk 0
    float4 ra, rb0, rb1;
    {
        int k0 = kb;
        ra  = *reinterpret_cast<const float4*>(&g_h2[rA * NN + k0 + cA]);
        rb0 = *reinterpret_cast<const float4*>(&w3[(size_t)(k0 + rB) * NN + n0 + cB]);
        rb1 = *reinterpret_cast<const float4*>(&w3[(size_t)(k0 + rB + 8) * NN + n0 + cB]);
    }

    // per-thread ldmatrix smem addresses (buffer 0; buffer 1 = +bufstride)
    uint32_t aAh = (uint32_t)__cvta_generic_to_shared(
        &sAh[0][(lane & 15)][(lane >> 4) * 8]);
    uint32_t aAl = (uint32_t)__cvta_generic_to_shared(
        &sAl[0][(lane & 15)][(lane >> 4) * 8]);
    uint32_t aBh = (uint32_t)__cvta_generic_to_shared(
        &sBh[0][(lane & 15)][warp * 16]);
    uint32_t aBl = (uint32_t)__cvta_generic_to_shared(
        &sBl[0][(lane & 15)][warp * 16]);
    const uint32_t strideAbuf = MB * 16 * 2;        // bytes per A buffer
    const uint32_t strideBbuf = 16 * GEMM_BN * 2;   // bytes per B buffer

    int p = 0;
#pragma unroll 1
    for (int ck = 0; ck < GEMM_NCHUNK; ck++) {
        // convert prefetched regs -> smem[p]
        {
            uint32_t h0, l0, h1, l1;
            split2(ra.x, ra.y, h0, l0);
            split2(ra.z, ra.w, h1, l1);
            *reinterpret_cast<uint2*>(&sAh[p][rA][cA]) = make_uint2(h0, h1);
            *reinterpret_cast<uint2*>(&sAl[p][rA][cA]) = make_uint2(l0, l1);

            split2(rb0.x, rb0.y, h0, l0);
            split2(rb0.z, rb0.w, h1, l1);
            *reinterpret_cast<uint2*>(&sBh[p][rB][cB]) = make_uint2(h0, h1);
            *reinterpret_cast<uint2*>(&sBl[p][rB][cB]) = make_uint2(l0, l1);

            split2(rb1.x, rb1.y, h0, l0);
            split2(rb1.z, rb1.w, h1, l1);
            *reinterpret_cast<uint2*>(&sBh[p][rB + 8][cB]) = make_uint2(h0, h1);
            *reinterpret_cast<uint2*>(&sBl[p][rB + 8][cB]) = make_uint2(l0, l1);
        }
        // prefetch next chunk
        if (ck + 1 < GEMM_NCHUNK) {
            int k0 = kb + (ck + 1) * 16;
            ra  = *reinterpret_cast<const float4*>(&g_h2[rA * NN + k0 + cA]);
            rb0 = *reinterpret_cast<const float4*>(&w3[(size_t)(k0 + rB) * NN + n0 + cB]);
            rb1 = *reinterpret_cast<const float4*>(&w3[(size_t)(k0 + rB + 8) * NN + n0 + cB]);
        }
        __syncthreads();

        // fragment loads + mma
        uint32_t aH[4][4], aL[4][4];
#pragma unroll
        for (int mi = 0; mi < 4; mi++) {
            ldsm_x4(aH[mi], aAh + p * strideAbuf + mi * 16 * 16 * 2);
            ldsm_x4(aL[mi], aAl + p * strideAbuf + mi * 16 * 16 * 2);
        }
        uint32_t bH[2][2], bL[2][2];
#pragma unroll
        for (int ni = 0; ni < 2; ni++) {
            ldsm_x2t(bH[ni], aBh + p * strideBbuf + ni * 8 * 2);
            ldsm_x2t(bL[ni], aBl + p * strideBbuf + ni * 8 * 2);
        }
#pragma unroll
        for (int mi = 0; mi < 4; mi++)
#pragma unroll
            for (int ni = 0; ni < 2; ni++) {
                mma_bf16(acc[mi][ni], aH[mi], bH[ni]);
                mma_bf16(acc[mi][ni], aH[mi], bL[ni]);
                mma_bf16(acc[mi][ni], aL[mi], bH[ni]);
            }
        p ^= 1;
    }

    // epilogue: atomic accumulate (split-K)
#pragma unroll
    for (int mi = 0; mi < 4; mi++) {
        int row = mi * 16 + g;
#pragma unroll
        for (int ni = 0; ni < 2; ni++) {
            int col = n0 + warp * 16 + ni * 8 + 2 * tg;
            atomicAdd(&out2[(size_t)row * NN + col],           acc[mi][ni][0]);
            atomicAdd(&out2[(size_t)row * NN + col + 1],       acc[mi][ni][1]);
            atomicAdd(&out2[(size_t)(row + 8) * NN + col],     acc[mi][ni][2]);
            atomicAdd(&out2[(size_t)(row + 8) * NN + col + 1], acc[mi][ni][3]);
        }
    }
}

// ---------------- launch ----------------------------------------------------
extern "C" void kernel_launch(void* const* d_in, const int* in_sizes, int n_in,
                              void* d_out, int out_size) {
    const float* feat = (const float*)d_in[0];
    const int*   src  = (const int*)d_in[1];
    const int*   dst  = (const int*)d_in[2];
    const float* ws1  = (const float*)d_in[3];
    const float* wn1  = (const float*)d_in[4];
    const float* b1   = (const float*)d_in[5];
    const float* ws2  = (const float*)d_in[6];
    const float* wn2  = (const float*)d_in[7];
    const float* b2   = (const float*)d_in[8];
    const float* w3   = (const float*)d_in[9];
    const float* b3   = (const float*)d_in[10];
    float* out = (float*)d_out;

    int N = in_sizes[0];   // 262144
    int E = in_sizes[1];   // 2097152

    k_zero<<<(N / 4 + 255) / 256, 256>>>(N / 4);
    k_edge1<<<(E + 255) / 256, 256>>>(feat, src, dst, E);
    k_node1<<<(N + 255) / 256, 256>>>(feat, ws1, wn1, b1, ws2, wn2, N);
    k_edge2<<<(E + 255) / 256, 256>>>(src, dst, E);
    k_node2<<<(N + 255) / 256, 256>>>(b2, b3, out, N);

    dim3 grid(NN / GEMM_BN, GEMM_KSPLIT);
    k_gemm<<<grid, 256>>>(w3, out + N);
}

// round 3
// speedup vs baseline: 1.3598x; 1.0762x over previous
#include <cuda_runtime.h>
#include <cuda_bf16.h>
#include <cstdint>

// Shapes (fixed for this problem)
#define N_TOTAL (64 * 4096)      // 262144 nodes
#define NHID    128
#define NN      4096             // nodes per graph == w3 dim
#define MB      64               // batch (graphs)

// ---------------- scratch (device globals; no allocation allowed) ----------
__device__ __align__(16) float2 g_fd [N_TOTAL];   // {agg1, deg} interleaved
__device__ float g_s   [N_TOTAL];
__device__ float g_t   [N_TOTAL];
__device__ float g_agg2[N_TOTAL];
__device__ float g_h2  [N_TOTAL];                 // tanh(output1): GEMM A
#define GEMM_KSPLIT 8
__device__ float g_part[GEMM_KSPLIT * N_TOTAL];   // split-K partials (8MB)

#define C_2LOG2E 2.88539008177792681f   // 2*log2(e)

// tanh via MUFU: input is PRESCALED xp = 2*log2e*x.
// tanh(x) = 1 - 2/(exp2(xp)+1).
__device__ __forceinline__ float tanh_exp2(float xp) {
    float e;
    asm("ex2.approx.f32 %0, %1;" : "=f"(e) : "f"(xp));
    float r;
    asm("rcp.approx.f32 %0, %1;" : "=f"(r) : "f"(e + 1.0f));
    return fmaf(-2.0f, r, 1.0f);
}

// ---------------- kernel 0: zero scratch (vectorized) -----------------------
__global__ void k_zero(int n4) {   // n4 = N_TOTAL/4
    int i = blockIdx.x * blockDim.x + threadIdx.x;
    if (i < n4) {
        float4 z = make_float4(0.f, 0.f, 0.f, 0.f);
        reinterpret_cast<float4*>(g_fd)[2 * i]     = z;
        reinterpret_cast<float4*>(g_fd)[2 * i + 1] = z;
        reinterpret_cast<float4*>(g_agg2)[i]       = z;
    }
}

// ---------------- kernel 1: edge scatter pass 1 ({agg1,deg} v2 red) ---------
__global__ void k_edge1(const float* __restrict__ feat,
                        const int* __restrict__ src,
                        const int* __restrict__ dst, int E) {
    int e = blockIdx.x * blockDim.x + threadIdx.x;
    if (e < E) {
        int s = src[e];
        int d = dst[e];
        float v = __ldg(&feat[s]);
        asm volatile("red.global.add.v2.f32 [%0], {%1, %2};"
                     :: "l"(g_fd + d), "f"(v), "f"(1.0f) : "memory");
    }
}

// ---------------- kernel 2: per-node 128-wide tanh layer --------------------
__global__ __launch_bounds__(256) void k_node1(
        const float* __restrict__ feat,
        const float* __restrict__ ws1, const float* __restrict__ wn1,
        const float* __restrict__ b1,
        const float* __restrict__ ws2, const float* __restrict__ wn2,
        int n_total) {
    __shared__ float4 wA[NHID];   // {C*ws1, C*wn1, C*b1, ws2}  (prescaled)
    __shared__ float  wB[NHID];   // wn2
    int t = threadIdx.x;
    if (t < NHID) {
        wA[t] = make_float4(C_2LOG2E * ws1[t], C_2LOG2E * wn1[t],
                            C_2LOG2E * b1[t], ws2[t]);
        wB[t] = wn2[t];
    }
    __syncthreads();

    int n = blockIdx.x * blockDim.x + t;
    if (n >= n_total) return;

    float f   = feat[n];
    float2 fd = g_fd[n];
    float g   = __fdividef(fd.x, fmaxf(fd.y, 1.0f));

    float sacc = 0.0f, tacc = 0.0f;
#pragma unroll 8
    for (int j = 0; j < NHID; j++) {
        float4 w = wA[j];
        float xp = fmaf(f, w.x, fmaf(g, w.y, w.z));
        float r = tanh_exp2(xp);
        sacc = fmaf(r, w.w, sacc);
        tacc = fmaf(r, wB[j], tacc);
    }
    g_s[n] = sacc;
    g_t[n] = tacc;
}

// ---------------- kernel 3: edge scatter pass 2 (agg2 of t) -----------------
__global__ void k_edge2(const int* __restrict__ src,
                        const int* __restrict__ dst, int E) {
    int e = blockIdx.x * blockDim.x + threadIdx.x;
    if (e < E) {
        atomicAdd(&g_agg2[dst[e]], __ldg(&g_t[src[e]]));
    }
}

// ---------------- kernel 4: out1, h2 = tanh(out1) ---------------------------
__global__ void k_node2(const float* __restrict__ b2,
                        float* __restrict__ out, int n_total) {
    int n = blockIdx.x * blockDim.x + threadIdx.x;
    if (n < n_total) {
        float o = g_s[n] + __fdividef(g_agg2[n], fmaxf(g_fd[n].y, 1.0f)) + b2[0];
        out[n] = o;                          // output1
        g_h2[n] = tanh_exp2(C_2LOG2E * o);
    }
}

// ---------------- kernel 5: GEMM partials: g_part = h2 @ w3 (bf16 split) ----
// 3 passes: Ah*Bh + Ah*Bl + Al*Bh via mma.m16n8k16.bf16 (rel err ~2^-17).
// Grid: 32 n-tiles (BN=128) x KSPLIT=8 (K range 512, 32 chunks of 16).
// Register prefetch + double-buffered smem; NON-ATOMIC v2 partial stores.
#define GEMM_BN 128
#define GEMM_KRANGE (NN / GEMM_KSPLIT)   // 512
#define GEMM_NCHUNK (GEMM_KRANGE / 16)   // 32

__device__ __forceinline__ void mma_bf16(float c[4], const uint32_t a[4],
                                         const uint32_t b[2]) {
    asm volatile(
        "mma.sync.aligned.m16n8k16.row.col.f32.bf16.bf16.f32 "
        "{%0,%1,%2,%3}, {%4,%5,%6,%7}, {%8,%9}, {%0,%1,%2,%3};\n"
        : "+f"(c[0]), "+f"(c[1]), "+f"(c[2]), "+f"(c[3])
        : "r"(a[0]), "r"(a[1]), "r"(a[2]), "r"(a[3]), "r"(b[0]), "r"(b[1]));
}

__device__ __forceinline__ void ldsm_x4(uint32_t r[4], uint32_t addr) {
    asm volatile("ldmatrix.sync.aligned.m8n8.x4.shared.b16 {%0,%1,%2,%3}, [%4];"
                 : "=r"(r[0]), "=r"(r[1]), "=r"(r[2]), "=r"(r[3]) : "r"(addr));
}
__device__ __forceinline__ void ldsm_x2t(uint32_t r[2], uint32_t addr) {
    asm volatile("ldmatrix.sync.aligned.m8n8.x2.trans.shared.b16 {%0,%1}, [%2];"
                 : "=r"(r[0]), "=r"(r[1]) : "r"(addr));
}

__device__ __forceinline__ void split2(float a, float b,
                                       uint32_t& hi, uint32_t& lo) {
    __nv_bfloat16 ha = __float2bfloat16_rn(a);
    __nv_bfloat16 hb = __float2bfloat16_rn(b);
    float la = a - __bfloat162float(ha);
    float lb = b - __bfloat162float(hb);
    __nv_bfloat16 hla = __float2bfloat16_rn(la);
    __nv_bfloat16 hlb = __float2bfloat16_rn(lb);
    hi = (uint32_t)*reinterpret_cast<unsigned short*>(&ha) |
         ((uint32_t)*reinterpret_cast<unsigned short*>(&hb) << 16);
    lo = (uint32_t)*reinterpret_cast<unsigned short*>(&hla) |
         ((uint32_t)*reinterpret_cast<unsigned short*>(&hlb) << 16);
}

__global__ __launch_bounds__(256) void k_gemm(const float* __restrict__ w3) {
    __shared__ __align__(16) unsigned short sAh[2][MB][16], sAl[2][MB][16];
    __shared__ __align__(16) unsigned short sBh[2][16][GEMM_BN], sBl[2][16][GEMM_BN];

    int tid  = threadIdx.x;
    int warp = tid >> 5;          // 0..7
    int lane = tid & 31;
    int g    = lane >> 2;
    int tg   = lane & 3;
    int n0   = blockIdx.x * GEMM_BN;
    int kb   = blockIdx.y * GEMM_KRANGE;

    int rA  = tid >> 2;            // 0..63
    int cA  = (tid & 3) * 4;
    int rB  = tid >> 5;            // 0..7 (and +8)
    int cB  = (tid & 31) * 4;

    float acc[4][2][4];
#pragma unroll
    for (int mi = 0; mi < 4; mi++)
#pragma unroll
        for (int ni = 0; ni < 2; ni++)
#pragma unroll
            for (int r = 0; r < 4; r++) acc[mi][ni][r] = 0.0f;

    float4 ra, rb0, rb1;
    {
        int k0 = kb;
        ra  = *reinterpret_cast<const float4*>(&g_h2[rA * NN + k0 + cA]);
        rb0 = *reinterpret_cast<const float4*>(&w3[(size_t)(k0 + rB) * NN + n0 + cB]);
        rb1 = *reinterpret_cast<const float4*>(&w3[(size_t)(k0 + rB + 8) * NN + n0 + cB]);
    }

    uint32_t aAh = (uint32_t)__cvta_generic_to_shared(
        &sAh[0][(lane & 15)][(lane >> 4) * 8]);
    uint32_t aAl = (uint32_t)__cvta_generic_to_shared(
        &sAl[0][(lane & 15)][(lane >> 4) * 8]);
    uint32_t aBh = (uint32_t)__cvta_generic_to_shared(
        &sBh[0][(lane & 15)][warp * 16]);
    uint32_t aBl = (uint32_t)__cvta_generic_to_shared(
        &sBl[0][(lane & 15)][warp * 16]);
    const uint32_t strideAbuf = MB * 16 * 2;
    const uint32_t strideBbuf = 16 * GEMM_BN * 2;

    int p = 0;
#pragma unroll 1
    for (int ck = 0; ck < GEMM_NCHUNK; ck++) {
        {
            uint32_t h0, l0, h1, l1;
            split2(ra.x, ra.y, h0, l0);
            split2(ra.z, ra.w, h1, l1);
            *reinterpret_cast<uint2*>(&sAh[p][rA][cA]) = make_uint2(h0, h1);
            *reinterpret_cast<uint2*>(&sAl[p][rA][cA]) = make_uint2(l0, l1);

            split2(rb0.x, rb0.y, h0, l0);
            split2(rb0.z, rb0.w, h1, l1);
            *reinterpret_cast<uint2*>(&sBh[p][rB][cB]) = make_uint2(h0, h1);
            *reinterpret_cast<uint2*>(&sBl[p][rB][cB]) = make_uint2(l0, l1);

            split2(rb1.x, rb1.y, h0, l0);
            split2(rb1.z, rb1.w, h1, l1);
            *reinterpret_cast<uint2*>(&sBh[p][rB + 8][cB]) = make_uint2(h0, h1);
            *reinterpret_cast<uint2*>(&sBl[p][rB + 8][cB]) = make_uint2(l0, l1);
        }
        if (ck + 1 < GEMM_NCHUNK) {
            int k0 = kb + (ck + 1) * 16;
            ra  = *reinterpret_cast<const float4*>(&g_h2[rA * NN + k0 + cA]);
            rb0 = *reinterpret_cast<const float4*>(&w3[(size_t)(k0 + rB) * NN + n0 + cB]);
            rb1 = *reinterpret_cast<const float4*>(&w3[(size_t)(k0 + rB + 8) * NN + n0 + cB]);
        }
        __syncthreads();

        uint32_t aH[4][4], aL[4][4];
#pragma unroll
        for (int mi = 0; mi < 4; mi++) {
            ldsm_x4(aH[mi], aAh + p * strideAbuf + mi * 16 * 16 * 2);
            ldsm_x4(aL[mi], aAl + p * strideAbuf + mi * 16 * 16 * 2);
        }
        uint32_t bH[2][2], bL[2][2];
#pragma unroll
        for (int ni = 0; ni < 2; ni++) {
            ldsm_x2t(bH[ni], aBh + p * strideBbuf + ni * 8 * 2);
            ldsm_x2t(bL[ni], aBl + p * strideBbuf + ni * 8 * 2);
        }
#pragma unroll
        for (int mi = 0; mi < 4; mi++)
#pragma unroll
            for (int ni = 0; ni < 2; ni++) {
                mma_bf16(acc[mi][ni], aH[mi], bH[ni]);
                mma_bf16(acc[mi][ni], aH[mi], bL[ni]);
                mma_bf16(acc[mi][ni], aL[mi], bH[ni]);
            }
        p ^= 1;
    }

    // epilogue: plain v2 stores into this split's partial slab (no atomics)
    float* part = g_part + (size_t)blockIdx.y * N_TOTAL;
#pragma unroll
    for (int mi = 0; mi < 4; mi++) {
        int row = mi * 16 + g;
#pragma unroll
        for (int ni = 0; ni < 2; ni++) {
            int col = n0 + warp * 16 + ni * 8 + 2 * tg;
            *reinterpret_cast<float2*>(&part[(size_t)row * NN + col]) =
                make_float2(acc[mi][ni][0], acc[mi][ni][1]);
            *reinterpret_cast<float2*>(&part[(size_t)(row + 8) * NN + col]) =
                make_float2(acc[mi][ni][2], acc[mi][ni][3]);
        }
    }
}

// ---------------- kernel 6: reduce split-K partials + b3 --------------------
__global__ void k_red(const float* __restrict__ b3,
                      float* __restrict__ out2, int n4) {  // n4 = N_TOTAL/4
    int i = blockIdx.x * blockDim.x + threadIdx.x;
    if (i < n4) {
        float4 a = reinterpret_cast<const float4*>(b3)[i & (NN / 4 - 1)];
#pragma unroll
        for (int j = 0; j < GEMM_KSPLIT; j++) {
            float4 pv = reinterpret_cast<const float4*>(g_part)[(size_t)j * (N_TOTAL / 4) + i];
            a.x += pv.x; a.y += pv.y; a.z += pv.z; a.w += pv.w;
        }
        reinterpret_cast<float4*>(out2)[i] = a;
    }
}

// ---------------- launch ----------------------------------------------------
extern "C" void kernel_launch(void* const* d_in, const int* in_sizes, int n_in,
                              void* d_out, int out_size) {
    const float* feat = (const float*)d_in[0];
    const int*   src  = (const int*)d_in[1];
    const int*   dst  = (const int*)d_in[2];
    const float* ws1  = (const float*)d_in[3];
    const float* wn1  = (const float*)d_in[4];
    const float* b1   = (const float*)d_in[5];
    const float* ws2  = (const float*)d_in[6];
    const float* wn2  = (const float*)d_in[7];
    const float* b2   = (const float*)d_in[8];
    const float* w3   = (const float*)d_in[9];
    const float* b3   = (const float*)d_in[10];
    float* out = (float*)d_out;

    int N = in_sizes[0];   // 262144
    int E = in_sizes[1];   // 2097152

    k_zero<<<(N / 4 + 255) / 256, 256>>>(N / 4);
    k_edge1<<<(E + 255) / 256, 256>>>(feat, src, dst, E);
    k_node1<<<(N + 255) / 256, 256>>>(feat, ws1, wn1, b1, ws2, wn2, N);
    k_edge2<<<(E + 255) / 256, 256>>>(src, dst, E);
    k_node2<<<(N + 255) / 256, 256>>>(b2, out, N);

    dim3 grid(NN / GEMM_BN, GEMM_KSPLIT);
    k_gemm<<<grid, 256>>>(w3);
    k_red<<<(N / 4 + 255) / 256, 256>>>(b3, out + N, N / 4);
}